// round 15
// baseline (speedup 1.0000x reference)
#include <cuda_runtime.h>
#include <cuda_bf16.h>
#include <cuda_fp16.h>
#include <cstdint>

// Problem constants (fixed by the dataset)
#define NN   100000      // nodes
#define EE   1600000     // edges
#define CAP  128         // adjacency bucket capacity per node
#define NSM  152         // GB300 SM count

// ---------------- scratch (device globals; no allocation allowed) ----------
__device__ __half  g_h0[(size_t)NN * 128];   // x @ W1 (fp16)
__device__ __half  g_h2[(size_t)NN * 64];    // relu(agg h0) @ W2 (fp16)
__device__ int     g_deg[NN];
__device__ int     g_adj[(size_t)NN * CAP];
__device__ __half  g_w1[128 * 128];          // W1^T, fp16
__device__ __half  g_w2[64 * 128];           // W2^T, fp16

#define ROWB 272   // smem row pitch: 128 halves (256B) + 16B pad, ldmatrix conflict-free

// ---------------- prep: clear degrees + W1/W2 transpose -> fp16 --------------
__global__ void k_prep(const float* __restrict__ W1, const float* __restrict__ W2,
                       __half* __restrict__ w1, __half* __restrict__ w2) {
    int i = blockIdx.x * blockDim.x + threadIdx.x;
    if (i < NN) g_deg[i] = 0;
    if (i < 128 * 128) {
        int k = i / 128, n = i % 128;
        w1[n * 128 + k] = __float2half_rn(W1[i]);
    } else if (i < 128 * 128 + 128 * 64) {
        int j = i - 128 * 128;
        int k = j / 64, n = j % 64;
        w2[n * 128 + k] = __float2half_rn(W2[j]);
    }
}

// ---------------- adjacency build: 4 edges/thread ---------------------------
__global__ void k_build_adj(const int* __restrict__ erow,
                            const int* __restrict__ ecol) {
    int e0 = (blockIdx.x * blockDim.x + threadIdx.x) * 4;
    if (e0 >= EE) return;
    int4 r = *reinterpret_cast<const int4*>(erow + e0);
    int4 c = *reinterpret_cast<const int4*>(ecol + e0);
    int p0 = atomicAdd(&g_deg[r.x], 1);
    int p1 = atomicAdd(&g_deg[r.y], 1);
    int p2 = atomicAdd(&g_deg[r.z], 1);
    int p3 = atomicAdd(&g_deg[r.w], 1);
    if (p0 < CAP) g_adj[(size_t)r.x * CAP + p0] = c.x;
    if (p1 < CAP) g_adj[(size_t)r.y * CAP + p1] = c.y;
    if (p2 < CAP) g_adj[(size_t)r.z * CAP + p2] = c.z;
    if (p3 < CAP) g_adj[(size_t)r.w * CAP + p3] = c.w;
}

// ---------------- mma / ldmatrix helpers -------------------------------------
#define LDMX4(r0, r1, r2, r3, addr) \
    asm volatile("ldmatrix.sync.aligned.m8n8.x4.shared.b16 {%0,%1,%2,%3}, [%4];" \
                 : "=r"(r0), "=r"(r1), "=r"(r2), "=r"(r3) : "r"(addr))
#define LDMX2(r0, r1, addr) \
    asm volatile("ldmatrix.sync.aligned.m8n8.x2.shared.b16 {%0,%1}, [%2];" \
                 : "=r"(r0), "=r"(r1) : "r"(addr))
#define MMA_F16(acc, a, b0, b1) \
    asm volatile("mma.sync.aligned.m16n8k16.row.col.f32.f16.f16.f32 " \
                 "{%0,%1,%2,%3}, {%4,%5,%6,%7}, {%8,%9}, {%0,%1,%2,%3};" \
                 : "+f"(acc[0]), "+f"(acc[1]), "+f"(acc[2]), "+f"(acc[3]) \
                 : "r"(a[0]), "r"(a[1]), "r"(a[2]), "r"(a[3]), "r"(b0), "r"(b1))

// ---------------- GEMM1: fp32 A -> fp16 single-pass, FULL-N (unchanged R14) --
__global__ __launch_bounds__(256, 2)
void k_gemm1(const float* __restrict__ A, const __half* __restrict__ B,
             __half* __restrict__ C, int nrows) {
    constexpr int NC = 128;
    constexpr int WN = 32, NT = 4;
    constexpr int B_BYTES = NC * ROWB;

    extern __shared__ char smem[];
    char* sB = smem;
    char* sA = smem + B_BYTES;

    const int tid = threadIdx.x;
    const int lane = tid & 31;
    const int wid = tid >> 5;
    const int g = lane >> 2;
    const int tg = lane & 3;
    const int mbase = (wid & 1) * 32;
    const int nbase = (wid >> 1) * WN;

    for (int i = tid; i < NC * 16; i += 256) {
        int n = i >> 4, q = i & 15;
        *reinterpret_cast<uint4*>(sB + n * ROWB + q * 16) =
            reinterpret_cast<const uint4*>(B + n * 128)[q];
    }

    const int rlm = lane & 7;
    const int qa = lane >> 3;
    uint32_t aA[2];
#pragma unroll
    for (int mt = 0; mt < 2; mt++) {
        int row = mbase + mt * 16 + (qa & 1) * 8 + rlm;
        int col = (qa >> 1) * 16;
        aA[mt] = (uint32_t)__cvta_generic_to_shared(sA) + row * ROWB + col;
    }
    const int lb = lane & 15;
    uint32_t aB[NT];
#pragma unroll
    for (int nt = 0; nt < NT; nt++) {
        int row = nbase + nt * 8 + (lb & 7);
        int col = ((lb >> 3) & 1) * 16;
        aB[nt] = (uint32_t)__cvta_generic_to_shared(sB) + row * ROWB + col;
    }

    const int ntiles = (nrows + 63) / 64;
    const int m0 = tid >> 5;
    const int q0 = tid & 31;

    float4 v[8];
    {
        const int r0 = blockIdx.x * 64;
#pragma unroll
        for (int it = 0; it < 8; it++) {
            int gr = r0 + m0 + it * 8;
            v[it] = (gr < nrows && (int)blockIdx.x < ntiles)
                ? *reinterpret_cast<const float4*>(A + (size_t)gr * 128 + q0 * 4)
                : make_float4(0.f, 0.f, 0.f, 0.f);
        }
    }

    for (int t = blockIdx.x; t < ntiles; t += gridDim.x) {
#pragma unroll
        for (int it = 0; it < 8; it++) {
            int m = m0 + it * 8;
            __half2 h01 = __float22half2_rn(make_float2(v[it].x, v[it].y));
            __half2 h23 = __float22half2_rn(make_float2(v[it].z, v[it].w));
            *reinterpret_cast<uint2*>(sA + m * ROWB + q0 * 8) = make_uint2(
                *reinterpret_cast<uint32_t*>(&h01), *reinterpret_cast<uint32_t*>(&h23));
        }
        __syncthreads();

        const int tn = t + gridDim.x;
        if (tn < ntiles) {
            const int rn = tn * 64;
#pragma unroll
            for (int it = 0; it < 8; it++) {
                int gr = rn + m0 + it * 8;
                v[it] = (gr < nrows)
                    ? *reinterpret_cast<const float4*>(A + (size_t)gr * 128 + q0 * 4)
                    : make_float4(0.f, 0.f, 0.f, 0.f);
            }
        }

        float acc[2][NT][4];
#pragma unroll
        for (int mt = 0; mt < 2; mt++)
#pragma unroll
            for (int nt = 0; nt < NT; nt++)
#pragma unroll
                for (int j = 0; j < 4; j++) acc[mt][nt][j] = 0.0f;

#pragma unroll
        for (int ks = 0; ks < 8; ks++) {
            const uint32_t ko = ks * 32;
            uint32_t a[2][4];
#pragma unroll
            for (int mt = 0; mt < 2; mt++)
                LDMX4(a[mt][0], a[mt][1], a[mt][2], a[mt][3], aA[mt] + ko);
#pragma unroll
            for (int nt = 0; nt < NT; nt++) {
                uint32_t b0, b1;
                LDMX2(b0, b1, aB[nt] + ko);
#pragma unroll
                for (int mt = 0; mt < 2; mt++)
                    MMA_F16(acc[mt][nt], a[mt], b0, b1);
            }
        }

        const int r0 = t * 64;
#pragma unroll
        for (int mt = 0; mt < 2; mt++) {
#pragma unroll
            for (int nt = 0; nt < NT; nt++) {
                int r1 = r0 + mbase + mt * 16 + g;
                int r2 = r1 + 8;
                int cc = nbase + nt * 8 + tg * 2;
                if (r1 < nrows)
                    *reinterpret_cast<__half2*>(C + (size_t)r1 * 128 + cc) =
                        __floats2half2_rn(acc[mt][nt][0], acc[mt][nt][1]);
                if (r2 < nrows)
                    *reinterpret_cast<__half2*>(C + (size_t)r2 * 128 + cc) =
                        __floats2half2_rn(acc[mt][nt][2], acc[mt][nt][3]);
            }
        }
        __syncthreads();
    }
}

// ---------------- FUSED: agg1 (mean+relu) -> smem -> gemm2 -------------------
// Per 64-row tile: 8 warps each aggregate 8 nodes of h0 into the smem A tile
// (fp16), then the CTA runs the gemm2 mainloop on it. h1 never touches gmem.
__global__ __launch_bounds__(256, 3)
void k_agg_gemm2(const __half* __restrict__ H0, const __half* __restrict__ B,
                 __half* __restrict__ C, int nrows) {
    constexpr int NCOL = 64;
    constexpr int WN = 16, NT = 2;
    constexpr int B_BYTES = NCOL * ROWB;

    extern __shared__ char smem[];
    char* sB = smem;
    char* sA = smem + B_BYTES;

    const int tid = threadIdx.x;
    const int lane = tid & 31;
    const int wid = tid >> 5;
    const int g = lane >> 2;
    const int tg = lane & 3;
    const int mbase = (wid & 1) * 32;
    const int nbase = (wid >> 1) * WN;

    // stage B (W2^T) once
    for (int i = tid; i < NCOL * 16; i += 256) {
        int n = i >> 4, q = i & 15;
        *reinterpret_cast<uint4*>(sB + n * ROWB + q * 16) =
            reinterpret_cast<const uint4*>(B + n * 128)[q];
    }

    // ldmatrix base addresses
    const int rlm = lane & 7;
    const int qa = lane >> 3;
    uint32_t aA[2];
#pragma unroll
    for (int mt = 0; mt < 2; mt++) {
        int row = mbase + mt * 16 + (qa & 1) * 8 + rlm;
        int col = (qa >> 1) * 16;
        aA[mt] = (uint32_t)__cvta_generic_to_shared(sA) + row * ROWB + col;
    }
    const int lb = lane & 15;
    uint32_t aB[NT];
#pragma unroll
    for (int nt = 0; nt < NT; nt++) {
        int row = nbase + nt * 8 + (lb & 7);
        int col = ((lb >> 3) & 1) * 16;
        aB[nt] = (uint32_t)__cvta_generic_to_shared(sB) + row * ROWB + col;
    }

    const int ntiles = (nrows + 63) / 64;

    for (int t = blockIdx.x; t < ntiles; t += gridDim.x) {
        const int r0 = t * 64;

        // ---- aggregation phase: warp w handles rows w*8 .. w*8+7 ------------
#pragma unroll 1
        for (int i = 0; i < 8; i++) {
            const int m = wid * 8 + i;
            const int node = r0 + m;
            float acc[4] = {0.f, 0.f, 0.f, 0.f};
            float inv = 0.0f;
            if (node < nrows) {
                const int d = g_deg[node];
                const int cnt = d < CAP ? d : CAP;
                const int* __restrict__ adj = g_adj + (size_t)node * CAP;
#pragma unroll 4
                for (int e = 0; e < cnt; e++) {
                    int j = __ldg(&adj[e]);
                    uint2 v = *reinterpret_cast<const uint2*>(
                        H0 + (size_t)j * 128 + lane * 4);
                    float2 f0 = __half22float2(*reinterpret_cast<__half2*>(&v.x));
                    float2 f1 = __half22float2(*reinterpret_cast<__half2*>(&v.y));
                    acc[0] += f0.x; acc[1] += f0.y; acc[2] += f1.x; acc[3] += f1.y;
                }
                inv = 1.0f / (float)d;
            }
            float o0 = fmaxf(acc[0] * inv, 0.f), o1 = fmaxf(acc[1] * inv, 0.f);
            float o2 = fmaxf(acc[2] * inv, 0.f), o3 = fmaxf(acc[3] * inv, 0.f);
            __half2 h01 = __float22half2_rn(make_float2(o0, o1));
            __half2 h23 = __float22half2_rn(make_float2(o2, o3));
            *reinterpret_cast<uint2*>(sA + m * ROWB + lane * 8) = make_uint2(
                *reinterpret_cast<uint32_t*>(&h01), *reinterpret_cast<uint32_t*>(&h23));
        }
        __syncthreads();

        // ---- MMA phase (gemm2 mainloop) --------------------------------------
        float acc[2][NT][4];
#pragma unroll
        for (int mt = 0; mt < 2; mt++)
#pragma unroll
            for (int nt = 0; nt < NT; nt++)
#pragma unroll
                for (int j = 0; j < 4; j++) acc[mt][nt][j] = 0.0f;

#pragma unroll
        for (int ks = 0; ks < 8; ks++) {
            const uint32_t ko = ks * 32;
            uint32_t a[2][4];
#pragma unroll
            for (int mt = 0; mt < 2; mt++)
                LDMX4(a[mt][0], a[mt][1], a[mt][2], a[mt][3], aA[mt] + ko);
#pragma unroll
            for (int nt = 0; nt < NT; nt++) {
                uint32_t b0, b1;
                LDMX2(b0, b1, aB[nt] + ko);
#pragma unroll
                for (int mt = 0; mt < 2; mt++)
                    MMA_F16(acc[mt][nt], a[mt], b0, b1);
            }
        }

        // ---- epilogue -> h2 ---------------------------------------------------
#pragma unroll
        for (int mt = 0; mt < 2; mt++) {
#pragma unroll
            for (int nt = 0; nt < NT; nt++) {
                int r1 = r0 + mbase + mt * 16 + g;
                int r2 = r1 + 8;
                int cc = nbase + nt * 8 + tg * 2;
                if (r1 < nrows)
                    *reinterpret_cast<__half2*>(C + (size_t)r1 * NCOL + cc) =
                        __floats2half2_rn(acc[mt][nt][0], acc[mt][nt][1]);
                if (r2 < nrows)
                    *reinterpret_cast<__half2*>(C + (size_t)r2 * NCOL + cc) =
                        __floats2half2_rn(acc[mt][nt][2], acc[mt][nt][3]);
            }
        }
        __syncthreads();
    }
}

// ---------------- agg2: mean, fp16 in -> fp32 out -----------------------------
__global__ void k_agg2(const __half* __restrict__ src, float* __restrict__ dst) {
    const int gw = (blockIdx.x * blockDim.x + threadIdx.x) >> 5;
    if (gw >= NN) return;
    const int lane = threadIdx.x & 31;

    const int d = g_deg[gw];
    const int cnt = d < CAP ? d : CAP;
    const int* __restrict__ adj = g_adj + (size_t)gw * CAP;

    float acc0 = 0.f, acc1 = 0.f;
#pragma unroll 4
    for (int t = 0; t < cnt; t++) {
        int j = __ldg(&adj[t]);
        uint32_t v = *reinterpret_cast<const uint32_t*>(src + (size_t)j * 64 + lane * 2);
        float2 f = __half22float2(*reinterpret_cast<__half2*>(&v));
        acc0 += f.x; acc1 += f.y;
    }
    const float inv = 1.0f / (float)d;
    *reinterpret_cast<float2*>(dst + (size_t)gw * 64 + lane * 2) =
        make_float2(acc0 * inv, acc1 * inv);
}

// ---------------- launch --------------------------------------------------------
extern "C" void kernel_launch(void* const* d_in, const int* in_sizes, int n_in,
                              void* d_out, int out_size) {
    const float* x    = (const float*)d_in[0];
    const float* W1   = (const float*)d_in[1];
    const float* W2   = (const float*)d_in[2];
    const int*   erow = (const int*)d_in[3];
    const int*   ecol = (const int*)d_in[4];
    float* out = (float*)d_out;

    __half *h0, *h2, *w1, *w2;
    cudaGetSymbolAddress((void**)&h0, g_h0);
    cudaGetSymbolAddress((void**)&h2, g_h2);
    cudaGetSymbolAddress((void**)&w1, g_w1);
    cudaGetSymbolAddress((void**)&w2, g_w2);

    const int SMEM1 = 128 * ROWB + 64 * ROWB;  // 52224 (B full + A tile)
    const int SMEM2 = 2 * 64 * ROWB;           // 34816 (B + A)
    cudaFuncSetAttribute(k_gemm1,     cudaFuncAttributeMaxDynamicSharedMemorySize, SMEM1);
    cudaFuncSetAttribute(k_agg_gemm2, cudaFuncAttributeMaxDynamicSharedMemorySize, SMEM2);

    // fork a side stream so build_adj overlaps prep + gemm1
    cudaStream_t s2;
    cudaStreamCreateWithFlags(&s2, cudaStreamNonBlocking);
    cudaEvent_t evFork, evJoin;
    cudaEventCreateWithFlags(&evFork, cudaEventDisableTiming);
    cudaEventCreateWithFlags(&evJoin, cudaEventDisableTiming);

    k_prep<<<(NN + 255) / 256, 256>>>(W1, W2, w1, w2);                            // 1
    cudaEventRecord(evFork, 0);
    cudaStreamWaitEvent(s2, evFork, 0);
    k_build_adj<<<(EE / 4 + 255) / 256, 256, 0, s2>>>(erow, ecol);                // 2 (side)
    cudaEventRecord(evJoin, s2);

    k_gemm1<<<2 * NSM, 256, SMEM1>>>(x, w1, h0, NN);                              // 3

    cudaStreamWaitEvent(0, evJoin, 0);   // adjacency ready before fused agg+gemm2
    k_agg_gemm2<<<3 * NSM, 256, SMEM2>>>(h0, w2, h2, NN);                         // 4 (slot 4)
    k_agg2<<<(NN * 32 + 255) / 256, 256>>>(h2, out);                              // 5

    cudaEventDestroy(evFork);
    cudaEventDestroy(evJoin);
    cudaStreamDestroy(s2);
}

// round 16
// speedup vs baseline: 1.1318x; 1.1318x over previous
#include <cuda_runtime.h>
#include <cuda_bf16.h>
#include <cuda_fp16.h>
#include <cstdint>

// Problem constants (fixed by the dataset)
#define NN   100000      // nodes
#define EE   1600000     // edges
#define CAP  128         // adjacency bucket capacity per node
#define NSM  152         // GB300 SM count

// ---------------- scratch (device globals; no allocation allowed) ----------
__device__ __half  g_h0[(size_t)NN * 128];   // x @ W1 (fp16)
__device__ __half  g_h1[(size_t)NN * 128];   // relu(agg h0) (fp16)
__device__ __half  g_h2[(size_t)NN * 64];    // h1 @ W2 (fp16)
__device__ int     g_deg[NN];
__device__ int     g_adj[(size_t)NN * CAP];
__device__ __half  g_w1[128 * 128];          // W1^T, fp16
__device__ __half  g_w2[64 * 128];           // W2^T, fp16

#define ROWB 272   // smem row pitch: 128 halves (256B) + 16B pad, ldmatrix conflict-free

// ---------------- prep 1: clear degrees + W1 transpose -> fp16 ---------------
__global__ void k_prep_w1(const float* __restrict__ W1, __half* __restrict__ w1) {
    int i = blockIdx.x * blockDim.x + threadIdx.x;
    if (i < NN) g_deg[i] = 0;
    if (i < 128 * 128) {
        int k = i / 128, n = i % 128;
        w1[n * 128 + k] = __float2half_rn(W1[i]);
    }
}

// ---------------- prep 2: W2 transpose -> fp16 --------------------------------
__global__ void k_prep_w2(const float* __restrict__ W2, __half* __restrict__ w2) {
    int i = blockIdx.x * blockDim.x + threadIdx.x;
    if (i < 128 * 64) {
        int k = i / 64, n = i % 64;
        w2[n * 128 + k] = __float2half_rn(W2[i]);
    }
}

// ---------------- adjacency build: 4 edges/thread ---------------------------
__global__ void k_build_adj(const int* __restrict__ erow,
                            const int* __restrict__ ecol) {
    int e0 = (blockIdx.x * blockDim.x + threadIdx.x) * 4;
    if (e0 >= EE) return;
    int4 r = *reinterpret_cast<const int4*>(erow + e0);
    int4 c = *reinterpret_cast<const int4*>(ecol + e0);
    int p0 = atomicAdd(&g_deg[r.x], 1);
    int p1 = atomicAdd(&g_deg[r.y], 1);
    int p2 = atomicAdd(&g_deg[r.z], 1);
    int p3 = atomicAdd(&g_deg[r.w], 1);
    if (p0 < CAP) g_adj[(size_t)r.x * CAP + p0] = c.x;
    if (p1 < CAP) g_adj[(size_t)r.y * CAP + p1] = c.y;
    if (p2 < CAP) g_adj[(size_t)r.z * CAP + p2] = c.z;
    if (p3 < CAP) g_adj[(size_t)r.w * CAP + p3] = c.w;
}

// ---------------- mma / ldmatrix helpers -------------------------------------
#define LDMX4(r0, r1, r2, r3, addr) \
    asm volatile("ldmatrix.sync.aligned.m8n8.x4.shared.b16 {%0,%1,%2,%3}, [%4];" \
                 : "=r"(r0), "=r"(r1), "=r"(r2), "=r"(r3) : "r"(addr))
#define LDMX2(r0, r1, addr) \
    asm volatile("ldmatrix.sync.aligned.m8n8.x2.shared.b16 {%0,%1}, [%2];" \
                 : "=r"(r0), "=r"(r1) : "r"(addr))
#define MMA_F16(acc, a, b0, b1) \
    asm volatile("mma.sync.aligned.m16n8k16.row.col.f32.f16.f16.f32 " \
                 "{%0,%1,%2,%3}, {%4,%5,%6,%7}, {%8,%9}, {%0,%1,%2,%3};" \
                 : "+f"(acc[0]), "+f"(acc[1]), "+f"(acc[2]), "+f"(acc[3]) \
                 : "r"(a[0]), "r"(a[1]), "r"(a[2]), "r"(a[3]), "r"(b0), "r"(b1))

// ---------------- GEMM1: fp32 A -> fp16, FULL-N, tile-per-CTA ----------------
// Output C[nrows,128](fp16). CTA = one 64x128 tile; latency hidden by 3 CTA/SM.
__global__ __launch_bounds__(256, 3)
void k_gemm1(const float* __restrict__ A, const __half* __restrict__ B,
             __half* __restrict__ C, int nrows) {
    constexpr int NC = 128;
    constexpr int WN = 32, NT = 4;
    constexpr int B_BYTES = NC * ROWB;

    extern __shared__ char smem[];
    char* sB = smem;
    char* sA = smem + B_BYTES;

    const int tid = threadIdx.x;
    const int lane = tid & 31;
    const int wid = tid >> 5;
    const int g = lane >> 2;
    const int tg = lane & 3;
    const int mbase = (wid & 1) * 32;
    const int nbase = (wid >> 1) * WN;
    const int r0 = blockIdx.x * 64;

    // stage B (w1 is L2-resident: 32KB reused by all CTAs)
    for (int i = tid; i < NC * 16; i += 256) {
        int n = i >> 4, q = i & 15;
        *reinterpret_cast<uint4*>(sB + n * ROWB + q * 16) =
            reinterpret_cast<const uint4*>(B + n * 128)[q];
    }

    // stage A: load fp32, convert to fp16, store (4-at-a-time batches)
    const int m0 = tid >> 5;    // rows m0, m0+8, ..., m0+56
    const int q0 = tid & 31;    // float4 column
#pragma unroll
    for (int it = 0; it < 8; it++) {
        int gr = r0 + m0 + it * 8;
        float4 v = (gr < nrows)
            ? *reinterpret_cast<const float4*>(A + (size_t)gr * 128 + q0 * 4)
            : make_float4(0.f, 0.f, 0.f, 0.f);
        __half2 h01 = __float22half2_rn(make_float2(v.x, v.y));
        __half2 h23 = __float22half2_rn(make_float2(v.z, v.w));
        *reinterpret_cast<uint2*>(sA + (m0 + it * 8) * ROWB + q0 * 8) = make_uint2(
            *reinterpret_cast<uint32_t*>(&h01), *reinterpret_cast<uint32_t*>(&h23));
    }

    // ldmatrix base addresses
    const int rlm = lane & 7;
    const int qa = lane >> 3;
    uint32_t aA[2];
#pragma unroll
    for (int mt = 0; mt < 2; mt++) {
        int row = mbase + mt * 16 + (qa & 1) * 8 + rlm;
        int col = (qa >> 1) * 16;
        aA[mt] = (uint32_t)__cvta_generic_to_shared(sA) + row * ROWB + col;
    }
    const int lb = lane & 15;
    uint32_t aB[NT];
#pragma unroll
    for (int nt = 0; nt < NT; nt++) {
        int row = nbase + nt * 8 + (lb & 7);
        int col = ((lb >> 3) & 1) * 16;
        aB[nt] = (uint32_t)__cvta_generic_to_shared(sB) + row * ROWB + col;
    }

    __syncthreads();

    float acc[2][NT][4];
#pragma unroll
    for (int mt = 0; mt < 2; mt++)
#pragma unroll
        for (int nt = 0; nt < NT; nt++)
#pragma unroll
            for (int j = 0; j < 4; j++) acc[mt][nt][j] = 0.0f;

#pragma unroll
    for (int ks = 0; ks < 8; ks++) {
        const uint32_t ko = ks * 32;
        uint32_t a[2][4];
#pragma unroll
        for (int mt = 0; mt < 2; mt++)
            LDMX4(a[mt][0], a[mt][1], a[mt][2], a[mt][3], aA[mt] + ko);
#pragma unroll
        for (int nt = 0; nt < NT; nt++) {
            uint32_t b0, b1;
            LDMX2(b0, b1, aB[nt] + ko);
#pragma unroll
            for (int mt = 0; mt < 2; mt++)
                MMA_F16(acc[mt][nt], a[mt], b0, b1);
        }
    }

#pragma unroll
    for (int mt = 0; mt < 2; mt++) {
#pragma unroll
        for (int nt = 0; nt < NT; nt++) {
            int r1 = r0 + mbase + mt * 16 + g;
            int r2 = r1 + 8;
            int cc = nbase + nt * 8 + tg * 2;
            if (r1 < nrows)
                *reinterpret_cast<__half2*>(C + (size_t)r1 * 128 + cc) =
                    __floats2half2_rn(acc[mt][nt][0], acc[mt][nt][1]);
            if (r2 < nrows)
                *reinterpret_cast<__half2*>(C + (size_t)r2 * 128 + cc) =
                    __floats2half2_rn(acc[mt][nt][2], acc[mt][nt][3]);
        }
    }
}

// ---------------- GEMM2: single fp16 A plane, single-pass (R14, proven) ------
__global__ __launch_bounds__(256, 3)
void k_gemm2(const __half* __restrict__ A, const __half* __restrict__ B,
             __half* __restrict__ C, int nrows) {
    constexpr int NCOL = 64;
    constexpr int WN = 16, NT = 2;
    constexpr int B_BYTES = NCOL * ROWB;

    extern __shared__ char smem[];
    char* sB = smem;
    char* sA = smem + B_BYTES;

    const int tid = threadIdx.x;
    const int lane = tid & 31;
    const int wid = tid >> 5;
    const int g = lane >> 2;
    const int tg = lane & 3;
    const int mbase = (wid & 1) * 32;
    const int nbase = (wid >> 1) * WN;

    for (int i = tid; i < NCOL * 16; i += 256) {
        int n = i >> 4, q = i & 15;
        *reinterpret_cast<uint4*>(sB + n * ROWB + q * 16) =
            reinterpret_cast<const uint4*>(B + n * 128)[q];
    }

    const int rlm = lane & 7;
    const int qa = lane >> 3;
    uint32_t aA[2];
#pragma unroll
    for (int mt = 0; mt < 2; mt++) {
        int row = mbase + mt * 16 + (qa & 1) * 8 + rlm;
        int col = (qa >> 1) * 16;
        aA[mt] = (uint32_t)__cvta_generic_to_shared(sA) + row * ROWB + col;
    }
    const int lb = lane & 15;
    uint32_t aB[NT];
#pragma unroll
    for (int nt = 0; nt < NT; nt++) {
        int row = nbase + nt * 8 + (lb & 7);
        int col = ((lb >> 3) & 1) * 16;
        aB[nt] = (uint32_t)__cvta_generic_to_shared(sB) + row * ROWB + col;
    }

    const int ntiles = (nrows + 63) / 64;
    const int m0 = tid >> 4;
    const int q0 = tid & 15;

    uint4 v[4];
    {
        const int r0 = blockIdx.x * 64;
#pragma unroll
        for (int it = 0; it < 4; it++) {
            int gr = r0 + m0 + it * 16;
            v[it] = (gr < nrows && (int)blockIdx.x < ntiles)
                ? reinterpret_cast<const uint4*>(A + (size_t)gr * 128)[q0]
                : make_uint4(0u, 0u, 0u, 0u);
        }
    }

    for (int t = blockIdx.x; t < ntiles; t += gridDim.x) {
#pragma unroll
        for (int it = 0; it < 4; it++)
            *reinterpret_cast<uint4*>(sA + (m0 + it * 16) * ROWB + q0 * 16) = v[it];
        __syncthreads();

        const int tn = t + gridDim.x;
        if (tn < ntiles) {
            const int rn = tn * 64;
#pragma unroll
            for (int it = 0; it < 4; it++) {
                int gr = rn + m0 + it * 16;
                v[it] = (gr < nrows)
                    ? reinterpret_cast<const uint4*>(A + (size_t)gr * 128)[q0]
                    : make_uint4(0u, 0u, 0u, 0u);
            }
        }

        float acc[2][NT][4];
#pragma unroll
        for (int mt = 0; mt < 2; mt++)
#pragma unroll
            for (int nt = 0; nt < NT; nt++)
#pragma unroll
                for (int j = 0; j < 4; j++) acc[mt][nt][j] = 0.0f;

#pragma unroll
        for (int ks = 0; ks < 8; ks++) {
            const uint32_t ko = ks * 32;
            uint32_t a[2][4];
#pragma unroll
            for (int mt = 0; mt < 2; mt++)
                LDMX4(a[mt][0], a[mt][1], a[mt][2], a[mt][3], aA[mt] + ko);
#pragma unroll
            for (int nt = 0; nt < NT; nt++) {
                uint32_t b0, b1;
                LDMX2(b0, b1, aB[nt] + ko);
#pragma unroll
                for (int mt = 0; mt < 2; mt++)
                    MMA_F16(acc[mt][nt], a[mt], b0, b1);
            }
        }

        const int r0 = t * 64;
#pragma unroll
        for (int mt = 0; mt < 2; mt++) {
#pragma unroll
            for (int nt = 0; nt < NT; nt++) {
                int r1 = r0 + mbase + mt * 16 + g;
                int r2 = r1 + 8;
                int cc = nbase + nt * 8 + tg * 2;
                if (r1 < nrows)
                    *reinterpret_cast<__half2*>(C + (size_t)r1 * NCOL + cc) =
                        __floats2half2_rn(acc[mt][nt][0], acc[mt][nt][1]);
                if (r2 < nrows)
                    *reinterpret_cast<__half2*>(C + (size_t)r2 * NCOL + cc) =
                        __floats2half2_rn(acc[mt][nt][2], acc[mt][nt][3]);
            }
        }
        __syncthreads();
    }
}

// ---------------- agg1: mean + relu, fp16 in -> fp16 out (R14, proven) -------
__global__ void k_agg1(const __half* __restrict__ src, __half* __restrict__ dst) {
    const int gw = (blockIdx.x * blockDim.x + threadIdx.x) >> 5;
    if (gw >= NN) return;
    const int lane = threadIdx.x & 31;

    const int d = g_deg[gw];
    const int cnt = d < CAP ? d : CAP;
    const int* __restrict__ adj = g_adj + (size_t)gw * CAP;

    float acc[4] = {0.f, 0.f, 0.f, 0.f};
#pragma unroll 4
    for (int t = 0; t < cnt; t++) {
        int j = __ldg(&adj[t]);
        uint2 v = *reinterpret_cast<const uint2*>(src + (size_t)j * 128 + lane * 4);
        float2 f0 = __half22float2(*reinterpret_cast<__half2*>(&v.x));
        float2 f1 = __half22float2(*reinterpret_cast<__half2*>(&v.y));
        acc[0] += f0.x; acc[1] += f0.y; acc[2] += f1.x; acc[3] += f1.y;
    }

    const float inv = 1.0f / (float)d;
    float o0 = fmaxf(acc[0] * inv, 0.f), o1 = fmaxf(acc[1] * inv, 0.f);
    float o2 = fmaxf(acc[2] * inv, 0.f), o3 = fmaxf(acc[3] * inv, 0.f);

    __half2 h01 = __float22half2_rn(make_float2(o0, o1));
    __half2 h23 = __float22half2_rn(make_float2(o2, o3));
    *reinterpret_cast<uint2*>(dst + (size_t)gw * 128 + lane * 4) = make_uint2(
        *reinterpret_cast<uint32_t*>(&h01), *reinterpret_cast<uint32_t*>(&h23));
}

// ---------------- agg2: mean, fp16 in -> fp32 out -----------------------------
__global__ void k_agg2(const __half* __restrict__ src, float* __restrict__ dst) {
    const int gw = (blockIdx.x * blockDim.x + threadIdx.x) >> 5;
    if (gw >= NN) return;
    const int lane = threadIdx.x & 31;

    const int d = g_deg[gw];
    const int cnt = d < CAP ? d : CAP;
    const int* __restrict__ adj = g_adj + (size_t)gw * CAP;

    float acc0 = 0.f, acc1 = 0.f;
#pragma unroll 4
    for (int t = 0; t < cnt; t++) {
        int j = __ldg(&adj[t]);
        uint32_t v = *reinterpret_cast<const uint32_t*>(src + (size_t)j * 64 + lane * 2);
        float2 f = __half22float2(*reinterpret_cast<__half2*>(&v));
        acc0 += f.x; acc1 += f.y;
    }
    const float inv = 1.0f / (float)d;
    *reinterpret_cast<float2*>(dst + (size_t)gw * 64 + lane * 2) =
        make_float2(acc0 * inv, acc1 * inv);
}

// ---------------- launch --------------------------------------------------------
extern "C" void kernel_launch(void* const* d_in, const int* in_sizes, int n_in,
                              void* d_out, int out_size) {
    const float* x    = (const float*)d_in[0];
    const float* W1   = (const float*)d_in[1];
    const float* W2   = (const float*)d_in[2];
    const int*   erow = (const int*)d_in[3];
    const int*   ecol = (const int*)d_in[4];
    float* out = (float*)d_out;

    __half *h0, *h1, *h2, *w1, *w2;
    cudaGetSymbolAddress((void**)&h0, g_h0);
    cudaGetSymbolAddress((void**)&h1, g_h1);
    cudaGetSymbolAddress((void**)&h2, g_h2);
    cudaGetSymbolAddress((void**)&w1, g_w1);
    cudaGetSymbolAddress((void**)&w2, g_w2);

    const int SMEM1 = 128 * ROWB + 64 * ROWB;  // 52224 (B full + A tile)
    const int SMEM2 = 2 * 64 * ROWB;           // 34816
    cudaFuncSetAttribute(k_gemm1, cudaFuncAttributeMaxDynamicSharedMemorySize, SMEM1);
    cudaFuncSetAttribute(k_gemm2, cudaFuncAttributeMaxDynamicSharedMemorySize, SMEM2);

    // fork a side stream so build_adj overlaps prep + gemm1
    cudaStream_t s2;
    cudaStreamCreateWithFlags(&s2, cudaStreamNonBlocking);
    cudaEvent_t evFork, evJoin;
    cudaEventCreateWithFlags(&evFork, cudaEventDisableTiming);
    cudaEventCreateWithFlags(&evJoin, cudaEventDisableTiming);

    k_prep_w1<<<(NN + 255) / 256, 256>>>(W1, w1);                                 // 1
    cudaEventRecord(evFork, 0);
    cudaStreamWaitEvent(s2, evFork, 0);
    k_build_adj<<<(EE / 4 + 255) / 256, 256, 0, s2>>>(erow, ecol);                // 2 (side)
    cudaEventRecord(evJoin, s2);

    k_prep_w2<<<(128 * 64 + 255) / 256, 256>>>(W2, w2);                           // 3
    k_gemm1<<<(NN + 63) / 64, 256, SMEM1>>>(x, w1, h0, NN);                       // 4 (slot 4)

    cudaStreamWaitEvent(0, evJoin, 0);   // adjacency ready before agg1
    k_agg1<<<(NN * 32 + 255) / 256, 256>>>(h0, h1);                               // 5
    k_gemm2<<<3 * NSM, 256, SMEM2>>>(h1, w2, h2, NN);                             // 6
    k_agg2<<<(NN * 32 + 255) / 256, 256>>>(h2, out);                              // 7

    cudaEventDestroy(evFork);
    cudaEventDestroy(evJoin);
    cudaStreamDestroy(s2);
}

// round 17
// speedup vs baseline: 1.1864x; 1.0483x over previous
#include <cuda_runtime.h>
#include <cuda_bf16.h>
#include <cuda_fp16.h>
#include <cstdint>

// Problem constants (fixed by the dataset)
#define NN   100000      // nodes
#define EE   1600000     // edges
#define CAP  128         // adjacency bucket capacity per node
#define NSM  152         // GB300 SM count
#define SPLIT 50048      // node split for agg1/gemm2 pipelining (multiple of 64)

// ---------------- scratch (device globals; no allocation allowed) ----------
__device__ __half  g_h0[(size_t)NN * 128];   // x @ W1 (fp16)
__device__ __half  g_h1[(size_t)NN * 128];   // relu(agg h0) (fp16)
__device__ __half  g_h2[(size_t)NN * 64];    // h1 @ W2 (fp16)
__device__ int     g_deg[NN];
__device__ int     g_adj[(size_t)NN * CAP];
__device__ __half  g_w1[128 * 128];          // W1^T, fp16
__device__ __half  g_w2[64 * 128];           // W2^T, fp16

#define ROWB 272   // smem row pitch: 128 halves (256B) + 16B pad, ldmatrix conflict-free

// ---------------- prep: clear degrees + W1/W2 transpose -> fp16 --------------
__global__ void k_prep(const float* __restrict__ W1, const float* __restrict__ W2,
                       __half* __restrict__ w1, __half* __restrict__ w2) {
    int i = blockIdx.x * blockDim.x + threadIdx.x;
    if (i < NN) g_deg[i] = 0;
    if (i < 128 * 128) {
        int k = i / 128, n = i % 128;
        w1[n * 128 + k] = __float2half_rn(W1[i]);
    } else if (i < 128 * 128 + 128 * 64) {
        int j = i - 128 * 128;
        int k = j / 64, n = j % 64;
        w2[n * 128 + k] = __float2half_rn(W2[j]);
    }
}

// ---------------- adjacency build: 4 edges/thread ---------------------------
__global__ void k_build_adj(const int* __restrict__ erow,
                            const int* __restrict__ ecol) {
    int e0 = (blockIdx.x * blockDim.x + threadIdx.x) * 4;
    if (e0 >= EE) return;
    int4 r = *reinterpret_cast<const int4*>(erow + e0);
    int4 c = *reinterpret_cast<const int4*>(ecol + e0);
    int p0 = atomicAdd(&g_deg[r.x], 1);
    int p1 = atomicAdd(&g_deg[r.y], 1);
    int p2 = atomicAdd(&g_deg[r.z], 1);
    int p3 = atomicAdd(&g_deg[r.w], 1);
    if (p0 < CAP) g_adj[(size_t)r.x * CAP + p0] = c.x;
    if (p1 < CAP) g_adj[(size_t)r.y * CAP + p1] = c.y;
    if (p2 < CAP) g_adj[(size_t)r.z * CAP + p2] = c.z;
    if (p3 < CAP) g_adj[(size_t)r.w * CAP + p3] = c.w;
}

// ---------------- mma / ldmatrix helpers -------------------------------------
#define LDMX4(r0, r1, r2, r3, addr) \
    asm volatile("ldmatrix.sync.aligned.m8n8.x4.shared.b16 {%0,%1,%2,%3}, [%4];" \
                 : "=r"(r0), "=r"(r1), "=r"(r2), "=r"(r3) : "r"(addr))
#define LDMX2(r0, r1, addr) \
    asm volatile("ldmatrix.sync.aligned.m8n8.x2.shared.b16 {%0,%1}, [%2];" \
                 : "=r"(r0), "=r"(r1) : "r"(addr))
#define MMA_F16(acc, a, b0, b1) \
    asm volatile("mma.sync.aligned.m16n8k16.row.col.f32.f16.f16.f32 " \
                 "{%0,%1,%2,%3}, {%4,%5,%6,%7}, {%8,%9}, {%0,%1,%2,%3};" \
                 : "+f"(acc[0]), "+f"(acc[1]), "+f"(acc[2]), "+f"(acc[3]) \
                 : "r"(a[0]), "r"(a[1]), "r"(a[2]), "r"(a[3]), "r"(b0), "r"(b1))

// ---------------- GEMM1: fp32 A -> fp16 single-pass, FULL-N (R14 exact) ------
__global__ __launch_bounds__(256, 2)
void k_gemm1(const float* __restrict__ A, const __half* __restrict__ B,
             __half* __restrict__ C, int nrows) {
    constexpr int NC = 128;
    constexpr int WN = 32, NT = 4;
    constexpr int B_BYTES = NC * ROWB;

    extern __shared__ char smem[];
    char* sB = smem;
    char* sA = smem + B_BYTES;

    const int tid = threadIdx.x;
    const int lane = tid & 31;
    const int wid = tid >> 5;
    const int g = lane >> 2;
    const int tg = lane & 3;
    const int mbase = (wid & 1) * 32;
    const int nbase = (wid >> 1) * WN;

    for (int i = tid; i < NC * 16; i += 256) {
        int n = i >> 4, q = i & 15;
        *reinterpret_cast<uint4*>(sB + n * ROWB + q * 16) =
            reinterpret_cast<const uint4*>(B + n * 128)[q];
    }

    const int rlm = lane & 7;
    const int qa = lane >> 3;
    uint32_t aA[2];
#pragma unroll
    for (int mt = 0; mt < 2; mt++) {
        int row = mbase + mt * 16 + (qa & 1) * 8 + rlm;
        int col = (qa >> 1) * 16;
        aA[mt] = (uint32_t)__cvta_generic_to_shared(sA) + row * ROWB + col;
    }
    const int lb = lane & 15;
    uint32_t aB[NT];
#pragma unroll
    for (int nt = 0; nt < NT; nt++) {
        int row = nbase + nt * 8 + (lb & 7);
        int col = ((lb >> 3) & 1) * 16;
        aB[nt] = (uint32_t)__cvta_generic_to_shared(sB) + row * ROWB + col;
    }

    const int ntiles = (nrows + 63) / 64;
    const int m0 = tid >> 5;
    const int q0 = tid & 31;

    float4 v[8];
    {
        const int r0 = blockIdx.x * 64;
#pragma unroll
        for (int it = 0; it < 8; it++) {
            int gr = r0 + m0 + it * 8;
            v[it] = (gr < nrows && (int)blockIdx.x < ntiles)
                ? *reinterpret_cast<const float4*>(A + (size_t)gr * 128 + q0 * 4)
                : make_float4(0.f, 0.f, 0.f, 0.f);
        }
    }

    for (int t = blockIdx.x; t < ntiles; t += gridDim.x) {
#pragma unroll
        for (int it = 0; it < 8; it++) {
            int m = m0 + it * 8;
            __half2 h01 = __float22half2_rn(make_float2(v[it].x, v[it].y));
            __half2 h23 = __float22half2_rn(make_float2(v[it].z, v[it].w));
            *reinterpret_cast<uint2*>(sA + m * ROWB + q0 * 8) = make_uint2(
                *reinterpret_cast<uint32_t*>(&h01), *reinterpret_cast<uint32_t*>(&h23));
        }
        __syncthreads();

        const int tn = t + gridDim.x;
        if (tn < ntiles) {
            const int rn = tn * 64;
#pragma unroll
            for (int it = 0; it < 8; it++) {
                int gr = rn + m0 + it * 8;
                v[it] = (gr < nrows)
                    ? *reinterpret_cast<const float4*>(A + (size_t)gr * 128 + q0 * 4)
                    : make_float4(0.f, 0.f, 0.f, 0.f);
            }
        }

        float acc[2][NT][4];
#pragma unroll
        for (int mt = 0; mt < 2; mt++)
#pragma unroll
            for (int nt = 0; nt < NT; nt++)
#pragma unroll
                for (int j = 0; j < 4; j++) acc[mt][nt][j] = 0.0f;

#pragma unroll
        for (int ks = 0; ks < 8; ks++) {
            const uint32_t ko = ks * 32;
            uint32_t a[2][4];
#pragma unroll
            for (int mt = 0; mt < 2; mt++)
                LDMX4(a[mt][0], a[mt][1], a[mt][2], a[mt][3], aA[mt] + ko);
#pragma unroll
            for (int nt = 0; nt < NT; nt++) {
                uint32_t b0, b1;
                LDMX2(b0, b1, aB[nt] + ko);
#pragma unroll
                for (int mt = 0; mt < 2; mt++)
                    MMA_F16(acc[mt][nt], a[mt], b0, b1);
            }
        }

        const int r0 = t * 64;
#pragma unroll
        for (int mt = 0; mt < 2; mt++) {
#pragma unroll
            for (int nt = 0; nt < NT; nt++) {
                int r1 = r0 + mbase + mt * 16 + g;
                int r2 = r1 + 8;
                int cc = nbase + nt * 8 + tg * 2;
                if (r1 < nrows)
                    *reinterpret_cast<__half2*>(C + (size_t)r1 * 128 + cc) =
                        __floats2half2_rn(acc[mt][nt][0], acc[mt][nt][1]);
                if (r2 < nrows)
                    *reinterpret_cast<__half2*>(C + (size_t)r2 * 128 + cc) =
                        __floats2half2_rn(acc[mt][nt][2], acc[mt][nt][3]);
            }
        }
        __syncthreads();
    }
}

// ---------------- GEMM2: fp16 A, single-pass, row range [r_lo, r_hi) ---------
__global__ __launch_bounds__(256, 3)
void k_gemm2(const __half* __restrict__ A, const __half* __restrict__ B,
             __half* __restrict__ C, int r_lo, int r_hi) {
    constexpr int NCOL = 64;
    constexpr int WN = 16, NT = 2;
    constexpr int B_BYTES = NCOL * ROWB;

    extern __shared__ char smem[];
    char* sB = smem;
    char* sA = smem + B_BYTES;

    const int tid = threadIdx.x;
    const int lane = tid & 31;
    const int wid = tid >> 5;
    const int g = lane >> 2;
    const int tg = lane & 3;
    const int mbase = (wid & 1) * 32;
    const int nbase = (wid >> 1) * WN;

    for (int i = tid; i < NCOL * 16; i += 256) {
        int n = i >> 4, q = i & 15;
        *reinterpret_cast<uint4*>(sB + n * ROWB + q * 16) =
            reinterpret_cast<const uint4*>(B + n * 128)[q];
    }

    const int rlm = lane & 7;
    const int qa = lane >> 3;
    uint32_t aA[2];
#pragma unroll
    for (int mt = 0; mt < 2; mt++) {
        int row = mbase + mt * 16 + (qa & 1) * 8 + rlm;
        int col = (qa >> 1) * 16;
        aA[mt] = (uint32_t)__cvta_generic_to_shared(sA) + row * ROWB + col;
    }
    const int lb = lane & 15;
    uint32_t aB[NT];
#pragma unroll
    for (int nt = 0; nt < NT; nt++) {
        int row = nbase + nt * 8 + (lb & 7);
        int col = ((lb >> 3) & 1) * 16;
        aB[nt] = (uint32_t)__cvta_generic_to_shared(sB) + row * ROWB + col;
    }

    const int ntiles = (r_hi - r_lo + 63) / 64;
    const int m0 = tid >> 4;
    const int q0 = tid & 15;

    uint4 v[4];
    {
        const int r0 = r_lo + blockIdx.x * 64;
#pragma unroll
        for (int it = 0; it < 4; it++) {
            int gr = r0 + m0 + it * 16;
            v[it] = (gr < r_hi && (int)blockIdx.x < ntiles)
                ? reinterpret_cast<const uint4*>(A + (size_t)gr * 128)[q0]
                : make_uint4(0u, 0u, 0u, 0u);
        }
    }

    for (int t = blockIdx.x; t < ntiles; t += gridDim.x) {
#pragma unroll
        for (int it = 0; it < 4; it++)
            *reinterpret_cast<uint4*>(sA + (m0 + it * 16) * ROWB + q0 * 16) = v[it];
        __syncthreads();

        const int tn = t + gridDim.x;
        if (tn < ntiles) {
            const int rn = r_lo + tn * 64;
#pragma unroll
            for (int it = 0; it < 4; it++) {
                int gr = rn + m0 + it * 16;
                v[it] = (gr < r_hi)
                    ? reinterpret_cast<const uint4*>(A + (size_t)gr * 128)[q0]
                    : make_uint4(0u, 0u, 0u, 0u);
            }
        }

        float acc[2][NT][4];
#pragma unroll
        for (int mt = 0; mt < 2; mt++)
#pragma unroll
            for (int nt = 0; nt < NT; nt++)
#pragma unroll
                for (int j = 0; j < 4; j++) acc[mt][nt][j] = 0.0f;

#pragma unroll
        for (int ks = 0; ks < 8; ks++) {
            const uint32_t ko = ks * 32;
            uint32_t a[2][4];
#pragma unroll
            for (int mt = 0; mt < 2; mt++)
                LDMX4(a[mt][0], a[mt][1], a[mt][2], a[mt][3], aA[mt] + ko);
#pragma unroll
            for (int nt = 0; nt < NT; nt++) {
                uint32_t b0, b1;
                LDMX2(b0, b1, aB[nt] + ko);
#pragma unroll
                for (int mt = 0; mt < 2; mt++)
                    MMA_F16(acc[mt][nt], a[mt], b0, b1);
            }
        }

        const int r0 = r_lo + t * 64;
#pragma unroll
        for (int mt = 0; mt < 2; mt++) {
#pragma unroll
            for (int nt = 0; nt < NT; nt++) {
                int r1 = r0 + mbase + mt * 16 + g;
                int r2 = r1 + 8;
                int cc = nbase + nt * 8 + tg * 2;
                if (r1 < r_hi)
                    *reinterpret_cast<__half2*>(C + (size_t)r1 * NCOL + cc) =
                        __floats2half2_rn(acc[mt][nt][0], acc[mt][nt][1]);
                if (r2 < r_hi)
                    *reinterpret_cast<__half2*>(C + (size_t)r2 * NCOL + cc) =
                        __floats2half2_rn(acc[mt][nt][2], acc[mt][nt][3]);
            }
        }
        __syncthreads();
    }
}

// ---------------- agg1: mean + relu, fp16 -> fp16, node range [n0, n1) -------
__global__ void k_agg1(const __half* __restrict__ src, __half* __restrict__ dst,
                       int n0, int n1) {
    const int gw = n0 + ((blockIdx.x * blockDim.x + threadIdx.x) >> 5);
    if (gw >= n1) return;
    const int lane = threadIdx.x & 31;

    const int d = g_deg[gw];
    const int cnt = d < CAP ? d : CAP;
    const int* __restrict__ adj = g_adj + (size_t)gw * CAP;

    float acc[4] = {0.f, 0.f, 0.f, 0.f};
#pragma unroll 4
    for (int t = 0; t < cnt; t++) {
        int j = __ldg(&adj[t]);
        uint2 v = *reinterpret_cast<const uint2*>(src + (size_t)j * 128 + lane * 4);
        float2 f0 = __half22float2(*reinterpret_cast<__half2*>(&v.x));
        float2 f1 = __half22float2(*reinterpret_cast<__half2*>(&v.y));
        acc[0] += f0.x; acc[1] += f0.y; acc[2] += f1.x; acc[3] += f1.y;
    }

    const float inv = 1.0f / (float)d;
    float o0 = fmaxf(acc[0] * inv, 0.f), o1 = fmaxf(acc[1] * inv, 0.f);
    float o2 = fmaxf(acc[2] * inv, 0.f), o3 = fmaxf(acc[3] * inv, 0.f);

    __half2 h01 = __float22half2_rn(make_float2(o0, o1));
    __half2 h23 = __float22half2_rn(make_float2(o2, o3));
    *reinterpret_cast<uint2*>(dst + (size_t)gw * 128 + lane * 4) = make_uint2(
        *reinterpret_cast<uint32_t*>(&h01), *reinterpret_cast<uint32_t*>(&h23));
}

// ---------------- agg2: mean, fp16 in -> fp32 out -----------------------------
__global__ void k_agg2(const __half* __restrict__ src, float* __restrict__ dst) {
    const int gw = (blockIdx.x * blockDim.x + threadIdx.x) >> 5;
    if (gw >= NN) return;
    const int lane = threadIdx.x & 31;

    const int d = g_deg[gw];
    const int cnt = d < CAP ? d : CAP;
    const int* __restrict__ adj = g_adj + (size_t)gw * CAP;

    float acc0 = 0.f, acc1 = 0.f;
#pragma unroll 4
    for (int t = 0; t < cnt; t++) {
        int j = __ldg(&adj[t]);
        uint32_t v = *reinterpret_cast<const uint32_t*>(src + (size_t)j * 64 + lane * 2);
        float2 f = __half22float2(*reinterpret_cast<__half2*>(&v));
        acc0 += f.x; acc1 += f.y;
    }
    const float inv = 1.0f / (float)d;
    *reinterpret_cast<float2*>(dst + (size_t)gw * 64 + lane * 2) =
        make_float2(acc0 * inv, acc1 * inv);
}

// ---------------- launch --------------------------------------------------------
extern "C" void kernel_launch(void* const* d_in, const int* in_sizes, int n_in,
                              void* d_out, int out_size) {
    const float* x    = (const float*)d_in[0];
    const float* W1   = (const float*)d_in[1];
    const float* W2   = (const float*)d_in[2];
    const int*   erow = (const int*)d_in[3];
    const int*   ecol = (const int*)d_in[4];
    float* out = (float*)d_out;

    __half *h0, *h1, *h2, *w1, *w2;
    cudaGetSymbolAddress((void**)&h0, g_h0);
    cudaGetSymbolAddress((void**)&h1, g_h1);
    cudaGetSymbolAddress((void**)&h2, g_h2);
    cudaGetSymbolAddress((void**)&w1, g_w1);
    cudaGetSymbolAddress((void**)&w2, g_w2);

    const int SMEM1 = 128 * ROWB + 64 * ROWB;  // 52224 (B full + A tile)
    const int SMEM2 = 2 * 64 * ROWB;           // 34816
    cudaFuncSetAttribute(k_gemm1, cudaFuncAttributeMaxDynamicSharedMemorySize, SMEM1);
    cudaFuncSetAttribute(k_gemm2, cudaFuncAttributeMaxDynamicSharedMemorySize, SMEM2);

    cudaStream_t s2;
    cudaStreamCreateWithFlags(&s2, cudaStreamNonBlocking);
    cudaEvent_t evFork, evJoin, evA0, evG0;
    cudaEventCreateWithFlags(&evFork, cudaEventDisableTiming);
    cudaEventCreateWithFlags(&evJoin, cudaEventDisableTiming);
    cudaEventCreateWithFlags(&evA0,   cudaEventDisableTiming);
    cudaEventCreateWithFlags(&evG0,   cudaEventDisableTiming);

    // 1) prep (weights + deg clear)
    k_prep<<<(NN + 255) / 256, 256>>>(W1, W2, w1, w2);

    // 2) adjacency build on side stream (overlaps gemm1)
    cudaEventRecord(evFork, 0);
    cudaStreamWaitEvent(s2, evFork, 0);
    k_build_adj<<<(EE / 4 + 255) / 256, 256, 0, s2>>>(erow, ecol);
    cudaEventRecord(evJoin, s2);

    // 3) gemm1 (R14-proven persistent)
    k_gemm1<<<2 * NSM, 256, SMEM1>>>(x, w1, h0, NN);

    // 4) agg1 half0, then (half1 || gemm2 half0 on side stream)
    cudaStreamWaitEvent(0, evJoin, 0);
    {
        const int w0 = SPLIT;                  // warps for half0
        k_agg1<<<(w0 * 32 + 255) / 256, 256>>>(h0, h1, 0, SPLIT);
    }
    cudaEventRecord(evA0, 0);

    {
        const int w1n = NN - SPLIT;
        k_agg1<<<(w1n * 32 + 255) / 256, 256>>>(h0, h1, SPLIT, NN);
    }
    cudaStreamWaitEvent(s2, evA0, 0);
    k_gemm2<<<2 * NSM, 256, SMEM2, s2>>>(h1, w2, h2, 0, SPLIT);
    cudaEventRecord(evG0, s2);

    // 5) gemm2 half1 on main (after agg1 half1, in stream order)
    k_gemm2<<<2 * NSM, 256, SMEM2>>>(h1, w2, h2, SPLIT, NN);

    // 6) agg2 after both gemm2 halves
    cudaStreamWaitEvent(0, evG0, 0);
    k_agg2<<<(NN * 32 + 255) / 256, 256>>>(h2, out);

    cudaEventDestroy(evFork);
    cudaEventDestroy(evJoin);
    cudaEventDestroy(evA0);
    cudaEventDestroy(evG0);
    cudaStreamDestroy(s2);
}